// round 14
// baseline (speedup 1.0000x reference)
#include <cuda_runtime.h>

#define TPB 256
#define RPT 8                      // rows per thread (4 packed pairs)
#define NPAIR (RPT / 2)
#define HID 64
#define BETA_C 0.99f
#define EPS_V 1e-3f
#define LOG_2PI 1.8378770664093453f
#define LOG2E 1.4426950408889634f
#define GRID 1024                  // B / (TPB*RPT) = 2097152 / 2048

__device__ float g_part[GRID];
__device__ unsigned int g_count;   // zero-init; last block resets to 0

typedef unsigned long long ull;

__device__ __forceinline__ ull pk2(float lo, float hi) {
    ull r; asm("mov.b64 %0, {%1,%2};" : "=l"(r) : "f"(lo), "f"(hi)); return r;
}
__device__ __forceinline__ void upk2(float& lo, float& hi, ull v) {
    asm("mov.b64 {%0,%1}, %2;" : "=f"(lo), "=f"(hi) : "l"(v));
}
__device__ __forceinline__ ull fma2(ull a, ull b, ull c) {
    ull d; asm("fma.rn.f32x2 %0, %1, %2, %3;" : "=l"(d) : "l"(a), "l"(b), "l"(c)); return d;
}
__device__ __forceinline__ ull mul2(ull a, ull b) {
    ull d; asm("mul.rn.f32x2 %0, %1, %2;" : "=l"(d) : "l"(a), "l"(b)); return d;
}
__device__ __forceinline__ ull relu2(ull v) {
    ull r;
    asm("{\n\t"
        ".reg .f32 lo, hi;\n\t"
        "mov.b64 {lo, hi}, %1;\n\t"
        "max.f32 lo, lo, 0f00000000;\n\t"
        "max.f32 hi, hi, 0f00000000;\n\t"
        "mov.b64 %0, {lo, hi};\n\t"
        "}" : "=l"(r) : "l"(v));
    return r;
}

// one 64-byte record per hidden unit -> exactly 4x LDS.128 per j, one base reg
struct __align__(16) WRec { ulonglong2 q0, q1, q2, q3; };
// q0 = (w0 dup, w1 dup) ; q1 = (b dup, w2c0 dup) ; q2 = (w2c1 dup, w2c2 dup)
// q3 = (w2c3 dup, pad)

__global__ __launch_bounds__(TPB, 3) void mdn_main(
    const float* __restrict__ x, const float* __restrict__ y,
    const float* __restrict__ eps,
    const float* __restrict__ W1, const float* __restrict__ b1,
    const float* __restrict__ W2, const float* __restrict__ b2,
    const float* __restrict__ Wv,
    float* __restrict__ out, int B)
{
    __shared__ WRec sW[HID];

    int tid = threadIdx.x;
    if (tid < HID) {
        float w0 = W1[tid], w1 = W1[HID + tid], bb = b1[tid];
        float4 w2 = *reinterpret_cast<const float4*>(W2 + 4 * tid);
        WRec r;
        reinterpret_cast<float4*>(&r.q0)[0] = make_float4(w0, w0, w1, w1);
        reinterpret_cast<float4*>(&r.q1)[0] = make_float4(bb, bb, w2.x, w2.x);
        reinterpret_cast<float4*>(&r.q2)[0] = make_float4(w2.y, w2.y, w2.z, w2.z);
        reinterpret_cast<float4*>(&r.q3)[0] = make_float4(w2.w, w2.w, 0.0f, 0.0f);
        sW[tid] = r;
    }
    __syncthreads();

    const float v00 = __ldg(Wv + 0), v01 = __ldg(Wv + 1);
    const float v10 = __ldg(Wv + 2), v11 = __ldg(Wv + 3);
    const float c0 = __ldg(b2 + 0), c1 = __ldg(b2 + 1);
    const float c2 = __ldg(b2 + 2), c3 = __ldg(b2 + 3);

    const int nth = GRID * TPB;
    const int g   = blockIdx.x * TPB + tid;

    ull xp0[NPAIR], xp1[NPAIR];          // packed (x0 row2p, x0 row2p+1), ditto x1
    ull a0[NPAIR], a1[NPAIR], a2[NPAIR], a3[NPAIR];

    #pragma unroll
    for (int p = 0; p < NPAIR; p++) {
        int r0 = g + (2 * p)     * nth;
        int r1 = g + (2 * p + 1) * nth;
        float2 xa = *reinterpret_cast<const float2*>(x + 2 * r0);
        float2 xb = *reinterpret_cast<const float2*>(x + 2 * r1);
        xp0[p] = pk2(xa.x, xb.x);
        xp1[p] = pk2(xa.y, xb.y);
        a0[p] = pk2(c0, c0); a1[p] = pk2(c1, c1);
        a2[p] = pk2(c2, c2); a3[p] = pk2(c3, c3);
    }

    // fully unrolled: no loop counter/branch, LDS.128 with immediate offsets,
    // ptxas free to hoist weight loads far ahead of use
    #pragma unroll
    for (int j = 0; j < HID; j++) {
        ulonglong2 q0 = sW[j].q0;    // (w0d, w1d)
        ulonglong2 q1 = sW[j].q1;    // (bd,  c0d)
        ulonglong2 q2 = sW[j].q2;    // (c1d, c2d)
        ull        c3d = sW[j].q3.x; // (c3d)
        #pragma unroll
        for (int p = 0; p < NPAIR; p++) {
            ull h = fma2(q0.x, xp0[p], fma2(q0.y, xp1[p], q1.x));
            h = relu2(h);
            a0[p] = fma2(q1.y, h, a0[p]);
            a1[p] = fma2(q2.x, h, a1[p]);
            a2[p] = fma2(q2.y, h, a2[p]);
            a3[p] = fma2(c3d,  h, a3[p]);
        }
    }

    // packed Lyapunov terms per pair
    const ull v00d = pk2(v00, v00), v01d = pk2(v01, v01);
    const ull v10d = pk2(v10, v10), v11d = pk2(v11, v11);
    const ull epsd = pk2(EPS_V, EPS_V);

    float tsum = 0.0f;
    #pragma unroll
    for (int p = 0; p < NPAIR; p++) {
        // Vx, Vmu computed packed across the row pair
        ull xa = fma2(v00d, xp0[p], mul2(v10d, xp1[p]));
        ull xb = fma2(v01d, xp0[p], mul2(v11d, xp1[p]));
        ull Vxp = fma2(xa, xa, fma2(xb, xb, epsd));
        ull ma = fma2(v00d, a0[p], mul2(v10d, a1[p]));
        ull mb = fma2(v01d, a0[p], mul2(v11d, a1[p]));
        ull Vmup = fma2(ma, ma, fma2(mb, mb, epsd));

        float VxA, VxB, VmuA, VmuB;
        upk2(VxA, VxB, Vxp); upk2(VmuA, VmuB, Vmup);

        float mu0a, mu0b, mu1a, mu1b, h2a, h2b, h3a, h3b;
        upk2(mu0a, mu0b, a0[p]); upk2(mu1a, mu1b, a1[p]);
        upk2(h2a,  h2b,  a2[p]); upk2(h3a,  h3b,  a3[p]);

        #pragma unroll
        for (int q = 0; q < 2; q++) {
            int r = g + (2 * p + q) * nth;
            float mu0 = q ? mu0b : mu0a, mu1 = q ? mu1b : mu1a;
            float h2  = q ? h2b  : h2a,  h3  = q ? h3b  : h3a;
            float Vx  = q ? VxB  : VxA,  Vmu = q ? VmuB : VmuA;

            // (b*Vx - relu(b*Vx - Vmu)) / Vmu == min(b*Vx/Vmu, 1)
            float s = fminf(__fdividef(BETA_C * Vx, Vmu), 1.0f);
            float ms0 = mu0 * s, ms1 = mu1 * s;

            float sd0 = exp2f(h2 * (0.5f * LOG2E));
            float sd1 = exp2f(h3 * (0.5f * LOG2E));
            float iv0 = exp2f(h2 * (-LOG2E));
            float iv1 = exp2f(h3 * (-LOG2E));

            float2 ev = *reinterpret_cast<const float2*>(eps + 2 * r);
            float2 yv = *reinterpret_cast<const float2*>(y + 2 * r);

            float2 fx;
            fx.x = fmaf(sd0, ev.x, ms0);
            fx.y = fmaf(sd1, ev.y, ms1);
            *reinterpret_cast<float2*>(out + 2 * r) = fx;

            float d0 = yv.x - ms0, d1 = yv.y - ms1;
            tsum += fmaf(d0 * d0, iv0, fmaf(d1 * d1, iv1, h2 + h3));
        }
    }

    // intra-block reduction
    #pragma unroll
    for (int o = 16; o > 0; o >>= 1)
        tsum += __shfl_down_sync(0xFFFFFFFFu, tsum, o);

    __shared__ float wsum[TPB / 32];
    if ((tid & 31) == 0) wsum[tid >> 5] = tsum;
    __syncthreads();

    __shared__ bool s_last;
    if (tid == 0) {
        float bs = 0.0f;
        #pragma unroll
        for (int w = 0; w < TPB / 32; w++) bs += wsum[w];
        g_part[blockIdx.x] = bs;
        __threadfence();
        unsigned int old = atomicAdd(&g_count, 1u);
        s_last = (old == GRID - 1);
    }
    __syncthreads();

    // last arriving block: deterministic fixed-order final reduce
    if (s_last) {
        __shared__ float red[TPB];
        float s = 0.0f;
        for (int i = tid; i < GRID; i += TPB) s += g_part[i];
        red[tid] = s;
        __syncthreads();
        #pragma unroll
        for (int o = TPB / 2; o > 0; o >>= 1) {
            if (tid < o) red[tid] += red[tid + o];
            __syncthreads();
        }
        if (tid == 0) {
            out[(size_t)2 * (size_t)B] = fmaf(0.5f, red[0], (float)B * LOG_2PI);
            g_count = 0;   // reset for next graph replay
        }
    }
}

extern "C" void kernel_launch(void* const* d_in, const int* in_sizes, int n_in,
                              void* d_out, int out_size)
{
    const float* x   = (const float*)d_in[0];
    const float* y   = (const float*)d_in[1];
    const float* eps = (const float*)d_in[2];
    const float* W1  = (const float*)d_in[3];
    const float* b1  = (const float*)d_in[4];
    const float* W2  = (const float*)d_in[5];
    const float* b2  = (const float*)d_in[6];
    const float* Wv  = (const float*)d_in[7];
    float* out = (float*)d_out;

    int B = in_sizes[0] / 2;   // 2,097,152
    mdn_main<<<GRID, TPB>>>(x, y, eps, W1, b1, W2, b2, Wv, out, B);
}